// round 1
// baseline (speedup 1.0000x reference)
#include <cuda_runtime.h>

// CostVolumeCorrelationLayer: B=8, H=W=128, C=128, maxDisp=4 -> 81 displacements
// out[b,y,x, dy*9+dx] = leaky_relu( mean_c( F1[b,y,x,c] * F2pad[b, y+dy, x+dx, c] ), 0.1 )
//   where F2pad is F2 zero-padded by 4 in y and x.

#define BB 8
#define HH 128
#define WW 128
#define CC_TOT 128
#define DMAX 4
#define KOFF 9
#define KDISP 81

#define CCH 16                 // channels per smem chunk
#define NCHUNK (CC_TOT / CCH)  // 8
#define NTHREADS 288
#define NWARPS 9

// padded row lengths in float2 units (pad map: i -> i + (i>>3))
#define F1_ROW 72   // 64 x-pairs, map(63)=70 -> 72
#define F2_ROW 76   // 68 x-pairs (x=-4..131), map(67)=75 -> 76

#define F2T_F2COUNT (9 * CCH * F2_ROW)   // 10944 float2
#define F1T_F2COUNT (CCH * F1_ROW)       // 1152 float2
#define SMEM_BYTES ((F2T_F2COUNT + F1T_F2COUNT) * 8)  // 96768 B

using ull = unsigned long long;

__device__ __forceinline__ int padmap(int i) { return i + (i >> 3); }

__device__ __forceinline__ void ffma2(ull &acc, ull a, ull b) {
    asm("fma.rn.f32x2 %0, %1, %2, %0;" : "+l"(acc) : "l"(a), "l"(b));
}

__global__ __launch_bounds__(NTHREADS, 2)
void corr_kernel(const float* __restrict__ F1,
                 const float* __restrict__ F2,
                 float* __restrict__ out)
{
    extern __shared__ float2 smem[];
    float2* F2t = smem;                      // [9][CCH][F2_ROW] float2 (x-pair major, transposed)
    float2* F1t = smem + F2T_F2COUNT;        // [CCH][F1_ROW]

    const int y   = blockIdx.x;
    const int b   = blockIdx.y;
    const int tid = threadIdx.x;
    const int w   = tid >> 5;    // warp = dy index 0..8
    const int g   = tid & 31;    // lane: owns pixels 4g..4g+3 (x-pairs 2g, 2g+1)

    // accumulators: acc[i][dx] packs outputs for pixels (4g+2i, 4g+2i+1)
    ull acc[2][9];
#pragma unroll
    for (int i = 0; i < 2; i++)
#pragma unroll
        for (int dx = 0; dx < 9; dx++) acc[i][dx] = 0ull;

    // precompute padded smem indices (channel-independent)
    const int p1a = padmap(2 * g);
    const int p1b = padmap(2 * g + 1);
    int pv[6];
#pragma unroll
    for (int j = 0; j < 6; j++) pv[j] = padmap(2 * g + j);

    const float* f1row = F1 + ((size_t)(b * HH + y)) * WW * CC_TOT;

    for (int ck = 0; ck < NCHUNK; ck++) {
        const int c0 = ck * CCH;
        __syncthreads();  // previous chunk's compute must finish before refill

        // ---- fill F2t: 9 halo rows, x = -4..131, channels c0..c0+15 (transpose on store) ----
        for (int q = tid; q < 9 * 136 * 4; q += NTHREADS) {
            int r   = q / (136 * 4);
            int rem = q - r * (136 * 4);
            int xi  = rem >> 2;            // 0..135 (stored x index; global x = xi-4)
            int cq  = rem & 3;             // channel quad within chunk
            int x   = xi - 4;
            int yy  = y + r - 4;
            float4 val = make_float4(0.f, 0.f, 0.f, 0.f);
            if (yy >= 0 && yy < HH && x >= 0 && x < WW) {
                val = *reinterpret_cast<const float4*>(
                    F2 + (((size_t)(b * HH + yy) * WW + x) * CC_TOT + c0 + 4 * cq));
            }
            int xp = xi >> 1;
            int sl = xi & 1;
            int base = (r * CCH + 4 * cq) * F2_ROW + padmap(xp);
            reinterpret_cast<float*>(F2t + base            )[sl] = val.x;
            reinterpret_cast<float*>(F2t + base + F2_ROW   )[sl] = val.y;
            reinterpret_cast<float*>(F2t + base + 2*F2_ROW )[sl] = val.z;
            reinterpret_cast<float*>(F2t + base + 3*F2_ROW )[sl] = val.w;
        }
        // ---- fill F1t: x = 0..127, channels c0..c0+15 ----
        for (int q = tid; q < 128 * 4; q += NTHREADS) {
            int xi = q >> 2;
            int cq = q & 3;
            float4 val = *reinterpret_cast<const float4*>(f1row + (size_t)xi * CC_TOT + c0 + 4 * cq);
            int xp = xi >> 1;
            int sl = xi & 1;
            int base = (4 * cq) * F1_ROW + padmap(xp);
            reinterpret_cast<float*>(F1t + base            )[sl] = val.x;
            reinterpret_cast<float*>(F1t + base + F1_ROW   )[sl] = val.y;
            reinterpret_cast<float*>(F1t + base + 2*F1_ROW )[sl] = val.z;
            reinterpret_cast<float*>(F1t + base + 3*F1_ROW )[sl] = val.w;
        }
        __syncthreads();

        // ---- accumulate this channel chunk ----
#pragma unroll 4
        for (int c = 0; c < CCH; c++) {
            const ull* f1r = reinterpret_cast<const ull*>(F1t + c * F1_ROW);
            const ull* f2r = reinterpret_cast<const ull*>(F2t + (w * CCH + c) * F2_ROW);

            ull f1a = f1r[p1a];   // pixels (4g, 4g+1) at channel c
            ull f1b = f1r[p1b];   // pixels (4g+2, 4g+3)

            ull v[6];
#pragma unroll
            for (int j = 0; j < 6; j++) v[j] = f2r[pv[j]];  // aligned F2 pairs, x = 4g-4 .. 4g+7

            // misaligned pairs m[j] = (v[j].hi, v[j+1].lo)  -> covers odd x starts
            ull m[5];
#pragma unroll
            for (int j = 0; j < 5; j++) {
                unsigned int lo = (unsigned int)(v[j] >> 32);
                unsigned int hi = (unsigned int)(v[j + 1]);
                asm("mov.b64 %0, {%1,%2};" : "=l"(m[j]) : "r"(lo), "r"(hi));
            }

            // even dx = 2e: acc[0] uses v[e], acc[1] uses v[e+1]
#pragma unroll
            for (int e = 0; e < 5; e++) {
                ffma2(acc[0][2 * e], f1a, v[e]);
                ffma2(acc[1][2 * e], f1b, v[e + 1]);
            }
            // odd dx = 2o+1: acc[0] uses m[o], acc[1] uses m[o+1]
#pragma unroll
            for (int o = 0; o < 4; o++) {
                ffma2(acc[0][2 * o + 1], f1a, m[o]);
                ffma2(acc[1][2 * o + 1], f1b, m[o + 1]);
            }
        }
    }

    // ---- finalize: mean + leaky relu, stage to smem, coalesced row store ----
    __syncthreads();
    float* ob = reinterpret_cast<float*>(smem);   // 128*81 floats = 41472 B (fits in F2t region)
    const float inv = 1.0f / 128.0f;
#pragma unroll
    for (int i = 0; i < 2; i++) {
        int px = 4 * g + 2 * i;
#pragma unroll
        for (int dx = 0; dx < 9; dx++) {
            ull a = acc[i][dx];
            float v0 = __uint_as_float((unsigned int)a) * inv;
            float v1 = __uint_as_float((unsigned int)(a >> 32)) * inv;
            v0 = v0 > 0.f ? v0 : 0.1f * v0;
            v1 = v1 > 0.f ? v1 : 0.1f * v1;
            int k = w * 9 + dx;
            ob[px * KDISP + k]       = v0;
            ob[(px + 1) * KDISP + k] = v1;
        }
    }
    __syncthreads();
    float* orow = out + ((size_t)(b * HH + y)) * WW * KDISP;
    const float4* obv = reinterpret_cast<const float4*>(ob);
    float4* ov = reinterpret_cast<float4*>(orow);
    for (int q = tid; q < (WW * KDISP) / 4; q += NTHREADS) {
        ov[q] = obv[q];
    }
}

extern "C" void kernel_launch(void* const* d_in, const int* in_sizes, int n_in,
                              void* d_out, int out_size)
{
    const float* F1 = (const float*)d_in[0];
    const float* F2 = (const float*)d_in[1];
    float* out = (float*)d_out;

    cudaFuncSetAttribute(corr_kernel, cudaFuncAttributeMaxDynamicSharedMemorySize, SMEM_BYTES);

    dim3 grid(HH, BB);     // (y, b) -> y-adjacent CTAs for L2 reuse of F2 halo rows
    dim3 block(NTHREADS);
    corr_kernel<<<grid, block, SMEM_BYTES>>>(F1, F2, out);
}

// round 2
// speedup vs baseline: 1.1084x; 1.1084x over previous
#include <cuda_runtime.h>

// CostVolumeCorrelationLayer: B=8, H=W=128, C=128, maxDisp=4 -> 81 displacements
// out[b,y,x, dy*9+dx] = leaky_relu( mean_c( F1[b,y,x,c] * F2pad[b, y+dy, x+dx, c] ), 0.1 )

#define BB 8
#define HH 128
#define WW 128
#define CC_TOT 128
#define KDISP 81

#define CCH 16                 // channels per smem chunk
#define NCHUNK (CC_TOT / CCH)  // 8
#define NTHREADS 288
#define NWARPS 9

// Row strides in float2 units. MUST satisfy ROW % 4 == 1 so that the fill's
// 4-channel store stride (4*ROW*2 floats) == 8 (mod 32) banks -> conflict-free STS.32.
// (76/72 gave stride == 0 mod 32 -> 4-way conflicts, ~half of all L1tex wavefronts.)
#define F1_ROW 73   // >= padmap(63)+1 = 71
#define F2_ROW 77   // >= padmap(67)+1 = 76

#define F2T_F2COUNT (9 * CCH * F2_ROW)   // 11088 float2
#define F1T_F2COUNT (CCH * F1_ROW)       // 1168 float2
#define SMEM_BYTES ((F2T_F2COUNT + F1T_F2COUNT) * 8)  // 98048 B

using ull = unsigned long long;

__device__ __forceinline__ int padmap(int i) { return i + (i >> 3); }

__device__ __forceinline__ void ffma2(ull &acc, ull a, ull b) {
    asm("fma.rn.f32x2 %0, %1, %2, %0;" : "+l"(acc) : "l"(a), "l"(b));
}

__global__ __launch_bounds__(NTHREADS, 2)
void corr_kernel(const float* __restrict__ F1,
                 const float* __restrict__ F2,
                 float* __restrict__ out)
{
    extern __shared__ float2 smem[];
    float2* F2t = smem;                      // [9][CCH][F2_ROW] float2 (x-pair major, transposed)
    float2* F1t = smem + F2T_F2COUNT;        // [CCH][F1_ROW]

    const int y   = blockIdx.x;
    const int b   = blockIdx.y;
    const int tid = threadIdx.x;
    const int w   = tid >> 5;    // warp = dy index 0..8
    const int g   = tid & 31;    // lane: owns pixels 4g..4g+3 (x-pairs 2g, 2g+1)

    // accumulators: acc[i][dx] packs outputs for pixels (4g+2i, 4g+2i+1)
    ull acc[2][9];
#pragma unroll
    for (int i = 0; i < 2; i++)
#pragma unroll
        for (int dx = 0; dx < 9; dx++) acc[i][dx] = 0ull;

    const int p1a = padmap(2 * g);
    const int p1b = padmap(2 * g + 1);
    int pv[6];
#pragma unroll
    for (int j = 0; j < 6; j++) pv[j] = padmap(2 * g + j);

    const float* f1row = F1 + ((size_t)(b * HH + y)) * WW * CC_TOT;

    for (int ck = 0; ck < NCHUNK; ck++) {
        const int c0 = ck * CCH;
        __syncthreads();  // previous chunk's compute must finish before refill

        // ---- fill F2t: 9 halo rows, x = -4..131, channels c0..c0+15 (transpose on store) ----
        for (int q = tid; q < 9 * 136 * 4; q += NTHREADS) {
            int r   = q / (136 * 4);
            int rem = q - r * (136 * 4);
            int xi  = rem >> 2;            // 0..135 (stored x index; global x = xi-4)
            int cq  = rem & 3;             // channel quad within chunk
            int x   = xi - 4;
            int yy  = y + r - 4;
            float4 val = make_float4(0.f, 0.f, 0.f, 0.f);
            if (yy >= 0 && yy < HH && x >= 0 && x < WW) {
                val = *reinterpret_cast<const float4*>(
                    F2 + (((size_t)(b * HH + yy) * WW + x) * CC_TOT + c0 + 4 * cq));
            }
            int xp = xi >> 1;
            int sl = xi & 1;
            int base = (r * CCH + 4 * cq) * F2_ROW + padmap(xp);
            reinterpret_cast<float*>(F2t + base            )[sl] = val.x;
            reinterpret_cast<float*>(F2t + base + F2_ROW   )[sl] = val.y;
            reinterpret_cast<float*>(F2t + base + 2*F2_ROW )[sl] = val.z;
            reinterpret_cast<float*>(F2t + base + 3*F2_ROW )[sl] = val.w;
        }
        // ---- fill F1t: x = 0..127, channels c0..c0+15 ----
        for (int q = tid; q < 128 * 4; q += NTHREADS) {
            int xi = q >> 2;
            int cq = q & 3;
            float4 val = *reinterpret_cast<const float4*>(f1row + (size_t)xi * CC_TOT + c0 + 4 * cq);
            int xp = xi >> 1;
            int sl = xi & 1;
            int base = (4 * cq) * F1_ROW + padmap(xp);
            reinterpret_cast<float*>(F1t + base            )[sl] = val.x;
            reinterpret_cast<float*>(F1t + base + F1_ROW   )[sl] = val.y;
            reinterpret_cast<float*>(F1t + base + 2*F1_ROW )[sl] = val.z;
            reinterpret_cast<float*>(F1t + base + 3*F1_ROW )[sl] = val.w;
        }
        __syncthreads();

        // ---- accumulate this channel chunk ----
#pragma unroll 4
        for (int c = 0; c < CCH; c++) {
            const ull* f1r = reinterpret_cast<const ull*>(F1t + c * F1_ROW);
            const ull* f2r = reinterpret_cast<const ull*>(F2t + (w * CCH + c) * F2_ROW);

            ull f1a = f1r[p1a];   // pixels (4g, 4g+1) at channel c
            ull f1b = f1r[p1b];   // pixels (4g+2, 4g+3)

            ull v[6];
#pragma unroll
            for (int j = 0; j < 6; j++) v[j] = f2r[pv[j]];  // aligned F2 pairs, x = 4g-4 .. 4g+7

            ull m[5];
#pragma unroll
            for (int j = 0; j < 5; j++) {
                unsigned int lo = (unsigned int)(v[j] >> 32);
                unsigned int hi = (unsigned int)(v[j + 1]);
                asm("mov.b64 %0, {%1,%2};" : "=l"(m[j]) : "r"(lo), "r"(hi));
            }

#pragma unroll
            for (int e = 0; e < 5; e++) {
                ffma2(acc[0][2 * e], f1a, v[e]);
                ffma2(acc[1][2 * e], f1b, v[e + 1]);
            }
#pragma unroll
            for (int o = 0; o < 4; o++) {
                ffma2(acc[0][2 * o + 1], f1a, m[o]);
                ffma2(acc[1][2 * o + 1], f1b, m[o + 1]);
            }
        }
    }

    // ---- finalize: mean + leaky relu, stage to smem, coalesced row store ----
    __syncthreads();
    float* ob = reinterpret_cast<float*>(smem);   // 128*81 floats = 41472 B
    const float inv = 1.0f / 128.0f;
#pragma unroll
    for (int i = 0; i < 2; i++) {
        int px = 4 * g + 2 * i;
#pragma unroll
        for (int dx = 0; dx < 9; dx++) {
            ull a = acc[i][dx];
            float v0 = __uint_as_float((unsigned int)a) * inv;
            float v1 = __uint_as_float((unsigned int)(a >> 32)) * inv;
            v0 = v0 > 0.f ? v0 : 0.1f * v0;
            v1 = v1 > 0.f ? v1 : 0.1f * v1;
            int k = w * 9 + dx;
            ob[px * KDISP + k]       = v0;
            ob[(px + 1) * KDISP + k] = v1;
        }
    }
    __syncthreads();
    float* orow = out + ((size_t)(b * HH + y)) * WW * KDISP;
    const float4* obv = reinterpret_cast<const float4*>(ob);
    float4* ov = reinterpret_cast<float4*>(orow);
    for (int q = tid; q < (WW * KDISP) / 4; q += NTHREADS) {
        ov[q] = obv[q];
    }
}

extern "C" void kernel_launch(void* const* d_in, const int* in_sizes, int n_in,
                              void* d_out, int out_size)
{
    const float* F1 = (const float*)d_in[0];
    const float* F2 = (const float*)d_in[1];
    float* out = (float*)d_out;

    cudaFuncSetAttribute(corr_kernel, cudaFuncAttributeMaxDynamicSharedMemorySize, SMEM_BYTES);

    dim3 grid(HH, BB);     // (y, b) -> y-adjacent CTAs for L2 reuse of F2 halo rows
    dim3 block(NTHREADS);
    corr_kernel<<<grid, block, SMEM_BYTES>>>(F1, F2, out);
}

// round 3
// speedup vs baseline: 1.6518x; 1.4903x over previous
#include <cuda_runtime.h>

// CostVolumeCorrelationLayer: B=8, H=W=128, C=128, maxDisp=4 -> 81 displacements
// out[b,y,x, dy*9+dx] = leaky_relu( mean_c( F1[b,y,x,c] * F2pad[b, y+dy, x+dx, c] ), 0.1 )
//
// Round-3 design:
//  - CTA = 2 output rows (y0, y0+1), 576 threads = 18 warps; warp = (row, dy).
//  - Lane g owns px 4g..4g+3; all compute loads are LDS.128 with 16B lane
//    stride (conflict-free). F2 window px 4g-4..4g+7 = 3 float4s.
//  - smem channel-transposed tiles; channel c stored in row rho(c)=(k<<3)|cq
//    (c=4cq+k), row stride 140 floats (140 mod 32 = 12) -> fill's 4-float
//    transpose scatter is bank-conflict-free: bank = (12*cq + xi) mod 32, all
//    32 lanes distinct. Fill LDG is 8 lanes x 16B = full 128B lines.
//  - CCH=32 channels/chunk, 4 chunks, 210KB dynamic smem, 1 CTA/SM.

#define BB 8
#define HH 128
#define WW 128
#define CC_TOT 128
#define KDISP 81

#define CCH 32
#define NCHUNK (CC_TOT / CCH)   // 4
#define NTHREADS 576
#define ROWS_PER_CTA 2
#define F2ROWS 10               // dy(0..8) + row(0..1) -> 0..9

#define ROW_F4 35               // f4 per channel row (needs 34 for F2), 140 floats
#define ROW_FLOATS (ROW_F4 * 4) // 140

#define F2T_F4 (F2ROWS * CCH * ROW_F4)        // 11200 f4
#define F1T_F4 (ROWS_PER_CTA * CCH * ROW_F4)  // 2240 f4
#define SMEM_BYTES ((F2T_F4 + F1T_F4) * 16)   // 215040 B

using ull = unsigned long long;

__device__ __forceinline__ void ffma2(ull &acc, ull a, ull b) {
    asm("fma.rn.f32x2 %0, %1, %2, %0;" : "+l"(acc) : "l"(a), "l"(b));
}

__global__ __launch_bounds__(NTHREADS, 1)
void corr_kernel(const float* __restrict__ F1,
                 const float* __restrict__ F2,
                 float* __restrict__ out)
{
    extern __shared__ float4 smem4[];
    float4* F2t = smem4;               // [10][CCH][ROW_F4]
    float4* F1t = smem4 + F2T_F4;      // [2][CCH][ROW_F4]

    const int y0  = blockIdx.x * 2;
    const int b   = blockIdx.y;
    const int tid = threadIdx.x;
    const int w   = tid >> 5;          // 0..17
    const int g   = tid & 31;
    const int row = (w >= 9) ? 1 : 0;  // output row within CTA
    const int dy  = w - 9 * row;       // 0..8

    ull acc[2][9];
#pragma unroll
    for (int i = 0; i < 2; i++)
#pragma unroll
        for (int dx = 0; dx < 9; dx++) acc[i][dx] = 0ull;

    float* F2tf = reinterpret_cast<float*>(F2t);
    float* F1tf = reinterpret_cast<float*>(F1t);

    for (int ck = 0; ck < NCHUNK; ck++) {
        const int c0 = ck * CCH;
        __syncthreads();   // previous chunk's compute done before refill

        // ---- F2 fill: 10 halo rows, xi=0..135 (x=xi-4), 8 channel-quads ----
        // q -> (r, xi, cq); lanes: cq=l&7 (128B contiguous in gmem), xi=l>>3.
        for (int q = tid; q < F2ROWS * 136 * 8; q += NTHREADS) {
            int r   = q / 1088;
            int rem = q - r * 1088;
            int xi  = rem >> 3;
            int cq  = rem & 7;
            int x   = xi - 4;
            int yy  = y0 + r - 4;
            float4 val = make_float4(0.f, 0.f, 0.f, 0.f);
            if (yy >= 0 && yy < HH && x >= 0 && x < WW) {
                val = __ldcg(reinterpret_cast<const float4*>(
                    F2 + (((size_t)(b * HH + yy) * WW + x) * CC_TOT + c0 + 4 * cq)));
            }
            // channel c = c0 + 4*cq + k  ->  smem row rho = k*8 + cq
            float* base = F2tf + (size_t)r * (CCH * ROW_FLOATS);
            base[(0 * 8 + cq) * ROW_FLOATS + xi] = val.x;
            base[(1 * 8 + cq) * ROW_FLOATS + xi] = val.y;
            base[(2 * 8 + cq) * ROW_FLOATS + xi] = val.z;
            base[(3 * 8 + cq) * ROW_FLOATS + xi] = val.w;
        }
        // ---- F1 fill: 2 rows, xi=0..127 ----
        for (int q = tid; q < ROWS_PER_CTA * 128 * 8; q += NTHREADS) {
            int r2  = q >> 10;
            int rem = q & 1023;
            int xi  = rem >> 3;
            int cq  = rem & 7;
            float4 val = __ldcg(reinterpret_cast<const float4*>(
                F1 + (((size_t)(b * HH + y0 + r2) * WW + xi) * CC_TOT + c0 + 4 * cq)));
            float* base = F1tf + (size_t)r2 * (CCH * ROW_FLOATS);
            base[(0 * 8 + cq) * ROW_FLOATS + xi] = val.x;
            base[(1 * 8 + cq) * ROW_FLOATS + xi] = val.y;
            base[(2 * 8 + cq) * ROW_FLOATS + xi] = val.z;
            base[(3 * 8 + cq) * ROW_FLOATS + xi] = val.w;
        }
        __syncthreads();

        // ---- accumulate: iterate smem channel-rows (order-independent sum) ----
        const ulonglong2* f1base =
            reinterpret_cast<const ulonglong2*>(F1t + (size_t)row * CCH * ROW_F4);
        const ulonglong2* f2base =
            reinterpret_cast<const ulonglong2*>(F2t + (size_t)(row + dy) * CCH * ROW_F4);

#pragma unroll 4
        for (int cr = 0; cr < CCH; cr++) {
            const ulonglong2* f1r = f1base + (size_t)cr * ROW_F4 * 2 / 2; // f4==u2 units
            const ulonglong2* f2r = f2base + (size_t)cr * ROW_F4;

            // NOTE: ulonglong2 == one float4 (16B). f4 index g etc.
            ulonglong2 A  = f1base[(size_t)cr * ROW_F4 + g];
            ulonglong2 V0 = f2base[(size_t)cr * ROW_F4 + g];
            ulonglong2 V1 = f2base[(size_t)cr * ROW_F4 + g + 1];
            ulonglong2 V2 = f2base[(size_t)cr * ROW_F4 + g + 2];
            (void)f1r; (void)f2r;

            ull f1a = A.x;   // px (4g, 4g+1)
            ull f1b = A.y;   // px (4g+2, 4g+3)
            ull vp[6] = { V0.x, V0.y, V1.x, V1.y, V2.x, V2.y }; // px 4g-4 .. 4g+7 pairs

            ull m[5];
#pragma unroll
            for (int j = 0; j < 5; j++) {
                unsigned int lo = (unsigned int)(vp[j] >> 32);
                unsigned int hi = (unsigned int)(vp[j + 1]);
                asm("mov.b64 %0, {%1,%2};" : "=l"(m[j]) : "r"(lo), "r"(hi));
            }

#pragma unroll
            for (int e = 0; e < 5; e++) {
                ffma2(acc[0][2 * e], f1a, vp[e]);
                ffma2(acc[1][2 * e], f1b, vp[e + 1]);
            }
#pragma unroll
            for (int o = 0; o < 4; o++) {
                ffma2(acc[0][2 * o + 1], f1a, m[o]);
                ffma2(acc[1][2 * o + 1], f1b, m[o + 1]);
            }
        }
    }

    // ---- finalize: mean + leaky relu; stage one row at a time; coalesced store ----
    float* ob = reinterpret_cast<float*>(smem4);  // 128*81 floats = 41472 B (fits)
    const float inv = 1.0f / 128.0f;

    for (int rowi = 0; rowi < ROWS_PER_CTA; rowi++) {
        __syncthreads();   // compute done / previous copy done
        if (row == rowi) {
#pragma unroll
            for (int i = 0; i < 2; i++) {
                int px = 4 * g + 2 * i;
#pragma unroll
                for (int dx = 0; dx < 9; dx++) {
                    ull a = acc[i][dx];
                    float v0 = __uint_as_float((unsigned int)a) * inv;
                    float v1 = __uint_as_float((unsigned int)(a >> 32)) * inv;
                    v0 = v0 > 0.f ? v0 : 0.1f * v0;
                    v1 = v1 > 0.f ? v1 : 0.1f * v1;
                    int k = dy * 9 + dx;
                    ob[px * KDISP + k]       = v0;
                    ob[(px + 1) * KDISP + k] = v1;
                }
            }
        }
        __syncthreads();
        float* orow = out + ((size_t)(b * HH + y0 + rowi)) * WW * KDISP;
        const float4* obv = reinterpret_cast<const float4*>(ob);
        float4* ov = reinterpret_cast<float4*>(orow);
        for (int q = tid; q < (WW * KDISP) / 4; q += NTHREADS) {
            ov[q] = obv[q];
        }
    }
}

extern "C" void kernel_launch(void* const* d_in, const int* in_sizes, int n_in,
                              void* d_out, int out_size)
{
    const float* F1 = (const float*)d_in[0];
    const float* F2 = (const float*)d_in[1];
    float* out = (float*)d_out;

    cudaFuncSetAttribute(corr_kernel, cudaFuncAttributeMaxDynamicSharedMemorySize, SMEM_BYTES);

    dim3 grid(HH / ROWS_PER_CTA, BB);   // (y-pair, b)
    dim3 block(NTHREADS);
    corr_kernel<<<grid, block, SMEM_BYTES>>>(F1, F2, out);
}